// round 3
// baseline (speedup 1.0000x reference)
#include <cuda_runtime.h>

#define N 4096
#define D 512
#define NCLASS 100

__device__ float g_zn[N * D];      // normalized z
__device__ float g_eadv[N];        // exp(cos(z, z_adv)/T)
__device__ float g_loss[N];
__device__ int   g_count[NCLASS];
__device__ int   g_offset[NCLASS];
__device__ int   g_members[N];     // row indices grouped by class (stable order)
__device__ int   g_lab[N];         // decoded int32 labels

__constant__ float c_invT = 2.0f;  // 1 / TEMPERATURE
__constant__ float c_eps  = 1e-8f;

// ---------------------------------------------------------------------------
// One block, 128 threads: detect int64-vs-int32 labels, decode into smem,
// histogram, offsets, and a STABLE O(N) counting sort into g_members.
// Thread t owns rows [t*32, t*32+32). Chunk-count -> per-class scan over
// chunks -> ordered emit. Fully deterministic, no cross-thread races in the
// ordering path.
// ---------------------------------------------------------------------------
__global__ void k_labels(const int* __restrict__ lab) {
    __shared__ int ok;
    __shared__ int sl[N];                       // 16 KB decoded labels
    __shared__ int cnt[NCLASS];
    __shared__ int coff[NCLASS];
    __shared__ unsigned short cb[NCLASS * 128]; // 25.6 KB chunk counts/bases
    int t = threadIdx.x;

    if (t == 0) ok = 1;
    __syncthreads();
    // Safe detect: only touch first 4096 int32 words (valid for both dtypes).
    // int64 labels in [0,100) => odd words zero, even words in range.
    bool good = true;
    for (int k = t; k < N / 2; k += 128) {
        int lo = lab[2 * k];
        int hi = lab[2 * k + 1];
        if (hi != 0 || lo < 0 || lo >= NCLASS) good = false;
    }
    if (!good) atomicExch(&ok, 0);
    __syncthreads();
    int is64 = ok;

    for (int i = t; i < N; i += 128) sl[i] = is64 ? lab[2 * i] : lab[i];
#pragma unroll 1
    for (int c = 0; c < NCLASS; c++) cb[c * 128 + t] = 0;
    __syncthreads();

    // per-chunk class counts (thread-private smem column -> no races)
    int rbase = t * 32;
#pragma unroll 1
    for (int r = 0; r < 32; r++) {
        int c = sl[rbase + r];
        cb[c * 128 + t]++;
    }
    __syncthreads();

    // per-class exclusive scan over the 128 chunks; thread c handles class c
    if (t < NCLASS) {
        int run = 0;
#pragma unroll 1
        for (int k = 0; k < 128; k++) {
            int v = cb[t * 128 + k];
            cb[t * 128 + k] = (unsigned short)run;
            run += v;
        }
        cnt[t] = run;
    }
    __syncthreads();

    if (t == 0) {
        int o = 0;
#pragma unroll 1
        for (int c = 0; c < NCLASS; c++) { coff[c] = o; o += cnt[c]; }
    }
    __syncthreads();

    // stable emit
#pragma unroll 1
    for (int r = 0; r < 32; r++) {
        int row = rbase + r;
        int c = sl[row];
        int pos = coff[c] + (int)cb[c * 128 + t];
        cb[c * 128 + t]++;
        g_members[pos] = row;
    }
    if (t < NCLASS) { g_count[t] = cnt[t]; g_offset[t] = coff[t]; }
    for (int i = t; i < N; i += 128) g_lab[i] = sl[i];
}

// ---------------------------------------------------------------------------
// Per-row: normalize z into g_zn, compute e_adv = exp(cos(z,z_adv)/T).
// 128 threads/block, one block per row, float4 loads.
// ---------------------------------------------------------------------------
__global__ void k_norm(const float* __restrict__ z, const float* __restrict__ za) {
    int row = blockIdx.x;
    int t = threadIdx.x;  // 0..127
    const float4* zr  = reinterpret_cast<const float4*>(z  + (size_t)row * D);
    const float4* zar = reinterpret_cast<const float4*>(za + (size_t)row * D);
    float4 v = zr[t];
    float4 w = zar[t];
    float sz = v.x * v.x + v.y * v.y + v.z * v.z + v.w * v.w;
    float sa = w.x * w.x + w.y * w.y + w.z * w.z + w.w * w.w;
    float dd = v.x * w.x + v.y * w.y + v.z * w.z + v.w * w.w;
#pragma unroll
    for (int o = 16; o; o >>= 1) {
        sz += __shfl_xor_sync(0xffffffffu, sz, o);
        sa += __shfl_xor_sync(0xffffffffu, sa, o);
        dd += __shfl_xor_sync(0xffffffffu, dd, o);
    }
    __shared__ float s1[4], s2[4], s3[4];
    int wid = t >> 5, lid = t & 31;
    if (lid == 0) { s1[wid] = sz; s2[wid] = sa; s3[wid] = dd; }
    __syncthreads();
    sz = s1[0] + s1[1] + s1[2] + s1[3];
    sa = s2[0] + s2[1] + s2[2] + s2[3];
    dd = s3[0] + s3[1] + s3[2] + s3[3];

    float invz  = 1.0f / fmaxf(sqrtf(sz), c_eps);
    float invza = 1.0f / fmaxf(sqrtf(sa), c_eps);

    float4 o4 = make_float4(v.x * invz, v.y * invz, v.z * invz, v.w * invz);
    reinterpret_cast<float4*>(g_zn + (size_t)row * D)[t] = o4;

    if (t == 0) g_eadv[row] = expf(dd * invz * invza * c_invT);
}

// ---------------------------------------------------------------------------
// Main: warp per member slot s. i = g_members[s]; adjacent warps share a
// class so class rows stay hot in L1/L2. Row i in 4 float4 regs; stream
// class members two at a time (two independent dot+shfl chains for ILP).
// ---------------------------------------------------------------------------
__global__ void k_intra() {
    int s = (blockIdx.x * blockDim.x + threadIdx.x) >> 5;
    int lane = threadIdx.x & 31;
    if (s >= N) return;
    int i = g_members[s];
    int c = g_lab[i];
    int off = g_offset[c];
    int cnt = g_count[c];

    const float4* zi = reinterpret_cast<const float4*>(g_zn + (size_t)i * D);
    float4 r0 = zi[lane], r1 = zi[lane + 32], r2 = zi[lane + 64], r3 = zi[lane + 96];

    float acc = 0.0f;
    int m = 0;
    for (; m + 2 <= cnt; m += 2) {
        int j0 = g_members[off + m];
        int j1 = g_members[off + m + 1];
        const float4* a = reinterpret_cast<const float4*>(g_zn + (size_t)j0 * D);
        const float4* b = reinterpret_cast<const float4*>(g_zn + (size_t)j1 * D);
        float s0 = 0.0f, s1 = 0.0f;
        float4 p, q;
        p = a[lane];       q = b[lane];
        s0 += r0.x*p.x + r0.y*p.y + r0.z*p.z + r0.w*p.w;
        s1 += r0.x*q.x + r0.y*q.y + r0.z*q.z + r0.w*q.w;
        p = a[lane + 32];  q = b[lane + 32];
        s0 += r1.x*p.x + r1.y*p.y + r1.z*p.z + r1.w*p.w;
        s1 += r1.x*q.x + r1.y*q.y + r1.z*q.z + r1.w*q.w;
        p = a[lane + 64];  q = b[lane + 64];
        s0 += r2.x*p.x + r2.y*p.y + r2.z*p.z + r2.w*p.w;
        s1 += r2.x*q.x + r2.y*q.y + r2.z*q.z + r2.w*q.w;
        p = a[lane + 96];  q = b[lane + 96];
        s0 += r3.x*p.x + r3.y*p.y + r3.z*p.z + r3.w*p.w;
        s1 += r3.x*q.x + r3.y*q.y + r3.z*q.z + r3.w*q.w;
#pragma unroll
        for (int o = 16; o; o >>= 1) {
            s0 += __shfl_xor_sync(0xffffffffu, s0, o);
            s1 += __shfl_xor_sync(0xffffffffu, s1, o);
        }
        float e0 = __expf(s0 * c_invT);
        float e1 = __expf(s1 * c_invT);
        acc += (j0 != i) ? e0 : 0.0f;
        acc += (j1 != i) ? e1 : 0.0f;
    }
    if (m < cnt) {
        int j0 = g_members[off + m];
        const float4* a = reinterpret_cast<const float4*>(g_zn + (size_t)j0 * D);
        float s0 = 0.0f;
#pragma unroll
        for (int k = 0; k < 4; k++) {
            float4 p = a[lane + 32 * k];
            float4 r = (k == 0) ? r0 : (k == 1) ? r1 : (k == 2) ? r2 : r3;
            s0 += r.x*p.x + r.y*p.y + r.z*p.z + r.w*p.w;
        }
#pragma unroll
        for (int o = 16; o; o >>= 1) s0 += __shfl_xor_sync(0xffffffffu, s0, o);
        acc += (j0 != i) ? __expf(s0 * c_invT) : 0.0f;
    }
    if (lane == 0) g_loss[i] = log1pf(acc / g_eadv[i]);
}

// ---------------------------------------------------------------------------
// Final reduction: out[0] = sum(loss)/N. Single block.
// ---------------------------------------------------------------------------
__global__ void k_reduce(float* __restrict__ out) {
    __shared__ float sm[256];
    int t = threadIdx.x;
    float s = 0.0f;
    for (int i = t; i < N; i += 256) s += g_loss[i];
    sm[t] = s;
    __syncthreads();
    for (int o = 128; o; o >>= 1) {
        if (t < o) sm[t] += sm[t + o];
        __syncthreads();
    }
    if (t == 0) out[0] = sm[0] * (1.0f / (float)N);
}

extern "C" void kernel_launch(void* const* d_in, const int* in_sizes, int n_in,
                              void* d_out, int out_size) {
    const float* z   = (const float*)d_in[0];
    const float* za  = (const float*)d_in[1];
    const int*   lab = (const int*)d_in[2];
    float* out = (float*)d_out;

    k_labels<<<1, 128>>>(lab);
    k_norm<<<N, 128>>>(z, za);
    k_intra<<<N / 8, 256>>>();   // 4096 warps, 8 warps/block
    k_reduce<<<1, 256>>>(out);
}

// round 5
// speedup vs baseline: 1.3170x; 1.3170x over previous
#include <cuda_runtime.h>

#define N 4096
#define D 512
#define NCLASS 100
#define INTRA_BLOCKS 512
#define INTRA_THREADS 256

__device__ float g_zn[N * D];      // normalized z
__device__ float g_eadv[N];        // exp(cos(z, z_adv)/T)
__device__ int   g_count[NCLASS];
__device__ int   g_offset[NCLASS];
__device__ int   g_members[N];     // row indices grouped by class (stable order)
__device__ int   g_lab[N];         // decoded int32 labels
__device__ float g_partial[INTRA_BLOCKS];
__device__ unsigned int g_done;

__constant__ float c_invT = 2.0f;  // 1 / TEMPERATURE
__constant__ float c_eps  = 1e-8f;

__device__ __forceinline__ int warp_incl_scan(int v, int lane) {
#pragma unroll
    for (int o = 1; o < 32; o <<= 1) {
        int y = __shfl_up_sync(0xffffffffu, v, o);
        if (lane >= o) v += y;
    }
    return v;
}

// ---------------------------------------------------------------------------
// One block, 128 threads: dtype detect, decode, STABLE O(N) counting sort.
// All scans warp-parallel (no serial thread-0 chains). Also resets g_done.
// ---------------------------------------------------------------------------
__global__ void k_labels(const int* __restrict__ lab) {
    __shared__ int ok;
    __shared__ int sl[N];                       // 16 KB decoded labels
    __shared__ int cnt[NCLASS];
    __shared__ int coff[NCLASS + 4];
    __shared__ unsigned short cb[NCLASS * 128]; // 25.6 KB chunk bases
    int t = threadIdx.x;
    int lane = t & 31, wid = t >> 5;

    if (t == 0) { ok = 1; g_done = 0u; }
    __syncthreads();
    // int64 labels in [0,100): odd 32-bit words are 0, even in range.
    bool good = true;
    for (int k = t; k < N / 2; k += 128) {
        int lo = lab[2 * k];
        int hi = lab[2 * k + 1];
        if (hi != 0 || lo < 0 || lo >= NCLASS) good = false;
    }
    if (!good) atomicExch(&ok, 0);
    __syncthreads();
    int is64 = ok;

    for (int i = t; i < N; i += 128) sl[i] = is64 ? lab[2 * i] : lab[i];
#pragma unroll 1
    for (int c = 0; c < NCLASS; c++) cb[c * 128 + t] = 0;
    __syncthreads();

    // per-chunk class counts (thread t owns rows [t*32, t*32+32))
    int rbase = t * 32;
#pragma unroll 1
    for (int r = 0; r < 32; r++) cb[sl[rbase + r] * 128 + t]++;
    __syncthreads();

    // exclusive scan over 128 chunks per class; warp-parallel, 4 warps x ~25 classes
    for (int c = wid; c < NCLASS; c += 4) {
        int carry = 0;
#pragma unroll
        for (int seg = 0; seg < 4; seg++) {
            int idx = c * 128 + seg * 32 + lane;
            int v = cb[idx];
            int inc = warp_incl_scan(v, lane);
            cb[idx] = (unsigned short)(inc - v + carry);
            carry += __shfl_sync(0xffffffffu, inc, 31);
        }
        if (lane == 0) cnt[c] = carry;
    }
    __syncthreads();

    // exclusive scan over 100 class counts; warp 0 only, segmented shfl scan
    if (wid == 0) {
        int carry = 0;
#pragma unroll
        for (int seg = 0; seg < 4; seg++) {
            int c = seg * 32 + lane;
            int v = (c < NCLASS) ? cnt[c] : 0;
            int inc = warp_incl_scan(v, lane);
            if (c < NCLASS) coff[c] = inc - v + carry;
            carry += __shfl_sync(0xffffffffu, inc, 31);
        }
    }
    __syncthreads();

    // stable emit
#pragma unroll 1
    for (int r = 0; r < 32; r++) {
        int row = rbase + r;
        int c = sl[row];
        int pos = coff[c] + (int)cb[c * 128 + t];
        cb[c * 128 + t]++;
        g_members[pos] = row;
    }
    if (t < NCLASS) { g_count[t] = cnt[t]; g_offset[t] = coff[t]; }
    for (int i = t; i < N; i += 128) g_lab[i] = sl[i];
}

// ---------------------------------------------------------------------------
// Per-row: normalize z into g_zn, compute e_adv = exp(cos(z,z_adv)/T).
// ---------------------------------------------------------------------------
__global__ void k_norm(const float* __restrict__ z, const float* __restrict__ za) {
    int row = blockIdx.x;
    int t = threadIdx.x;  // 0..127
    const float4* zr  = reinterpret_cast<const float4*>(z  + (size_t)row * D);
    const float4* zar = reinterpret_cast<const float4*>(za + (size_t)row * D);
    float4 v = zr[t];
    float4 w = zar[t];
    float sz = v.x * v.x + v.y * v.y + v.z * v.z + v.w * v.w;
    float sa = w.x * w.x + w.y * w.y + w.z * w.z + w.w * w.w;
    float dd = v.x * w.x + v.y * w.y + v.z * w.z + v.w * w.w;
#pragma unroll
    for (int o = 16; o; o >>= 1) {
        sz += __shfl_xor_sync(0xffffffffu, sz, o);
        sa += __shfl_xor_sync(0xffffffffu, sa, o);
        dd += __shfl_xor_sync(0xffffffffu, dd, o);
    }
    __shared__ float s1[4], s2[4], s3[4];
    int wid = t >> 5, lid = t & 31;
    if (lid == 0) { s1[wid] = sz; s2[wid] = sa; s3[wid] = dd; }
    __syncthreads();
    sz = s1[0] + s1[1] + s1[2] + s1[3];
    sa = s2[0] + s2[1] + s2[2] + s2[3];
    dd = s3[0] + s3[1] + s3[2] + s3[3];

    float invz  = 1.0f / fmaxf(sqrtf(sz), c_eps);
    float invza = 1.0f / fmaxf(sqrtf(sa), c_eps);

    float4 o4 = make_float4(v.x * invz, v.y * invz, v.z * invz, v.w * invz);
    reinterpret_cast<float4*>(g_zn + (size_t)row * D)[t] = o4;

    if (t == 0) g_eadv[row] = expf(dd * invz * invza * c_invT);
}

// ---------------------------------------------------------------------------
// Main: warp per member slot s (adjacent warps share a class -> L1 reuse).
// 2-way member unroll for ILP. Block partial -> g_partial; ticket last-block
// does the deterministic fixed-tree final reduction into out[0].
// ---------------------------------------------------------------------------
__global__ void k_intra(float* __restrict__ out) {
    __shared__ float warp_loss[INTRA_THREADS / 32];
    __shared__ bool is_last;
    int s = (blockIdx.x * blockDim.x + threadIdx.x) >> 5;
    int lane = threadIdx.x & 31;
    int wid = threadIdx.x >> 5;

    int i = g_members[s];
    int c = g_lab[i];
    int off = g_offset[c];
    int cnt = g_count[c];

    const float4* zi = reinterpret_cast<const float4*>(g_zn + (size_t)i * D);
    float4 r0 = zi[lane], r1 = zi[lane + 32], r2 = zi[lane + 64], r3 = zi[lane + 96];

    float acc = 0.0f;
    int m = 0;
    for (; m + 2 <= cnt; m += 2) {
        int j0 = g_members[off + m];
        int j1 = g_members[off + m + 1];
        const float4* a = reinterpret_cast<const float4*>(g_zn + (size_t)j0 * D);
        const float4* b = reinterpret_cast<const float4*>(g_zn + (size_t)j1 * D);
        float s0 = 0.0f, s1 = 0.0f;
        float4 p, q;
        p = a[lane];       q = b[lane];
        s0 += r0.x*p.x + r0.y*p.y + r0.z*p.z + r0.w*p.w;
        s1 += r0.x*q.x + r0.y*q.y + r0.z*q.z + r0.w*q.w;
        p = a[lane + 32];  q = b[lane + 32];
        s0 += r1.x*p.x + r1.y*p.y + r1.z*p.z + r1.w*p.w;
        s1 += r1.x*q.x + r1.y*q.y + r1.z*q.z + r1.w*q.w;
        p = a[lane + 64];  q = b[lane + 64];
        s0 += r2.x*p.x + r2.y*p.y + r2.z*p.z + r2.w*p.w;
        s1 += r2.x*q.x + r2.y*q.y + r2.z*q.z + r2.w*q.w;
        p = a[lane + 96];  q = b[lane + 96];
        s0 += r3.x*p.x + r3.y*p.y + r3.z*p.z + r3.w*p.w;
        s1 += r3.x*q.x + r3.y*q.y + r3.z*q.z + r3.w*q.w;
#pragma unroll
        for (int o = 16; o; o >>= 1) {
            s0 += __shfl_xor_sync(0xffffffffu, s0, o);
            s1 += __shfl_xor_sync(0xffffffffu, s1, o);
        }
        float e0 = __expf(s0 * c_invT);
        float e1 = __expf(s1 * c_invT);
        acc += (j0 != i) ? e0 : 0.0f;
        acc += (j1 != i) ? e1 : 0.0f;
    }
    if (m < cnt) {
        int j0 = g_members[off + m];
        const float4* a = reinterpret_cast<const float4*>(g_zn + (size_t)j0 * D);
        float s0 = 0.0f;
        float4 p;
        p = a[lane];       s0 += r0.x*p.x + r0.y*p.y + r0.z*p.z + r0.w*p.w;
        p = a[lane + 32];  s0 += r1.x*p.x + r1.y*p.y + r1.z*p.z + r1.w*p.w;
        p = a[lane + 64];  s0 += r2.x*p.x + r2.y*p.y + r2.z*p.z + r2.w*p.w;
        p = a[lane + 96];  s0 += r3.x*p.x + r3.y*p.y + r3.z*p.z + r3.w*p.w;
#pragma unroll
        for (int o = 16; o; o >>= 1) s0 += __shfl_xor_sync(0xffffffffu, s0, o);
        acc += (j0 != i) ? __expf(s0 * c_invT) : 0.0f;
    }

    // per-warp loss -> block partial (fixed order => deterministic)
    if (lane == 0) warp_loss[wid] = log1pf(acc / g_eadv[i]);
    __syncthreads();
    if (threadIdx.x == 0) {
        float bsum = 0.0f;
#pragma unroll
        for (int w = 0; w < INTRA_THREADS / 32; w++) bsum += warp_loss[w];
        g_partial[blockIdx.x] = bsum;
        __threadfence();
        unsigned int ticket = atomicAdd(&g_done, 1u);
        is_last = (ticket == INTRA_BLOCKS - 1);
    }
    __syncthreads();

    // last-arriving block: deterministic fixed-tree reduction of 512 partials
    if (is_last) {
        __shared__ float sm[INTRA_THREADS];
        int t = threadIdx.x;
        __threadfence();
        sm[t] = g_partial[t] + g_partial[t + INTRA_THREADS];
        __syncthreads();
#pragma unroll
        for (int o = INTRA_THREADS / 2; o > 0; o >>= 1) {
            if (t < o) sm[t] += sm[t + o];
            __syncthreads();
        }
        if (t == 0) out[0] = sm[0] * (1.0f / (float)N);
    }
}

extern "C" void kernel_launch(void* const* d_in, const int* in_sizes, int n_in,
                              void* d_out, int out_size) {
    const float* z   = (const float*)d_in[0];
    const float* za  = (const float*)d_in[1];
    const int*   lab = (const int*)d_in[2];
    float* out = (float*)d_out;

    k_labels<<<1, 128>>>(lab);
    k_norm<<<N, 128>>>(z, za);
    k_intra<<<INTRA_BLOCKS, INTRA_THREADS>>>(out);
}

// round 7
// speedup vs baseline: 1.4411x; 1.0942x over previous
#include <cuda_runtime.h>

#define N 4096
#define D 512
#define NCLASS 100
#define INTRA_BLOCKS 512
#define INTRA_THREADS 256

__device__ float g_zn[N * D];      // normalized z
__device__ float g_eadv[N];        // exp(cos(z, z_adv)/T)
__device__ int   g_count[NCLASS];
__device__ int   g_offset[NCLASS];
__device__ int   g_members[N];     // row indices grouped by class (stable order)
__device__ int   g_lab[N];         // decoded int32 labels
__device__ float g_partial[INTRA_BLOCKS];
__device__ unsigned int g_done;

__constant__ float c_invT = 2.0f;  // 1 / TEMPERATURE
__constant__ float c_eps  = 1e-8f;

// ---------------------------------------------------------------------------
// 1024 threads (32 warps), one block: dtype detect, decode, STABLE counting
// sort via __match_any_sync. Warp w owns rows [w*128, w*128+128).
// No long SHFL chains, no serial per-thread RMW loops. Resets g_done.
// ---------------------------------------------------------------------------
__global__ void k_labels(const int* __restrict__ lab) {
    __shared__ int sl[N];                 // 16 KB decoded labels
    __shared__ int whist[32][NCLASS];     // 12.8 KB per-warp class counts/bases
    __shared__ int cls_cnt[NCLASS];
    __shared__ int cls_off[NCLASS];
    __shared__ int ok;
    int t = threadIdx.x;
    int lane = t & 31, w = t >> 5;

    if (t == 0) { ok = 1; g_done = 0u; }
    __syncthreads();
    // int64 labels in [0,100): odd 32-bit words are 0, even in range.
    bool good = true;
    for (int k = t; k < N / 2; k += 1024) {
        int lo = lab[2 * k];
        int hi = lab[2 * k + 1];
        if (hi != 0 || lo < 0 || lo >= NCLASS) good = false;
    }
    if (!good) atomicExch(&ok, 0);
    __syncthreads();
    int is64 = ok;

    for (int i = t; i < N; i += 1024) sl[i] = is64 ? lab[2 * i] : lab[i];
    for (int c = lane; c < NCLASS; c += 32) whist[w][c] = 0;
    __syncthreads();

    // count pass: 4 iterations of 32 rows per warp, match_any + leader popc
    int rbase = w * 128;
#pragma unroll
    for (int it = 0; it < 4; it++) {
        int c = sl[rbase + it * 32 + lane];
        unsigned mask = __match_any_sync(0xffffffffu, c);
        int leader = __ffs(mask) - 1;
        if (lane == leader) whist[w][c] += __popc(mask);
        __syncwarp();
    }
    __syncthreads();

    // cross-warp exclusive scan per class (thread per class, pipelined LDS)
    if (t < NCLASS) {
        int run = 0;
#pragma unroll 1
        for (int k = 0; k < 32; k++) {
            int v = whist[k][t];
            whist[k][t] = run;
            run += v;
        }
        cls_cnt[t] = run;
    }
    __syncthreads();

    // class offsets: warp 0, 4 SHFL scan segments over 100 counts
    if (w == 0) {
        int carry = 0;
#pragma unroll
        for (int seg = 0; seg < 4; seg++) {
            int c = seg * 32 + lane;
            int v = (c < NCLASS) ? cls_cnt[c] : 0;
            int inc = v;
#pragma unroll
            for (int o = 1; o < 32; o <<= 1) {
                int y = __shfl_up_sync(0xffffffffu, inc, o);
                if (lane >= o) inc += y;
            }
            if (c < NCLASS) cls_off[c] = inc - v + carry;
            carry += __shfl_sync(0xffffffffu, inc, 31);
        }
    }
    __syncthreads();

    // stable emit: match_any rank within the 32-row group, leader bumps base
#pragma unroll
    for (int it = 0; it < 4; it++) {
        int row = rbase + it * 32 + lane;
        int c = sl[row];
        unsigned mask = __match_any_sync(0xffffffffu, c);
        int rank = __popc(mask & ((1u << lane) - 1u));
        int base = whist[w][c];          // same-class lanes broadcast-read
        g_members[cls_off[c] + base + rank] = row;
        int leader = __ffs(mask) - 1;
        if (lane == leader) whist[w][c] = base + __popc(mask);
        __syncwarp();
    }
    if (t < NCLASS) { g_count[t] = cls_cnt[t]; g_offset[t] = cls_off[t]; }
    for (int i = t; i < N; i += 1024) g_lab[i] = sl[i];
}

// ---------------------------------------------------------------------------
// Per-row: normalize z into g_zn, compute e_adv = exp(cos(z,z_adv)/T).
// ---------------------------------------------------------------------------
__global__ void k_norm(const float* __restrict__ z, const float* __restrict__ za) {
    int row = blockIdx.x;
    int t = threadIdx.x;  // 0..127
    const float4* zr  = reinterpret_cast<const float4*>(z  + (size_t)row * D);
    const float4* zar = reinterpret_cast<const float4*>(za + (size_t)row * D);
    float4 v = zr[t];
    float4 w = zar[t];
    float sz = v.x * v.x + v.y * v.y + v.z * v.z + v.w * v.w;
    float sa = w.x * w.x + w.y * w.y + w.z * w.z + w.w * w.w;
    float dd = v.x * w.x + v.y * w.y + v.z * w.z + v.w * w.w;
#pragma unroll
    for (int o = 16; o; o >>= 1) {
        sz += __shfl_xor_sync(0xffffffffu, sz, o);
        sa += __shfl_xor_sync(0xffffffffu, sa, o);
        dd += __shfl_xor_sync(0xffffffffu, dd, o);
    }
    __shared__ float s1[4], s2[4], s3[4];
    int wid = t >> 5, lid = t & 31;
    if (lid == 0) { s1[wid] = sz; s2[wid] = sa; s3[wid] = dd; }
    __syncthreads();
    sz = s1[0] + s1[1] + s1[2] + s1[3];
    sa = s2[0] + s2[1] + s2[2] + s2[3];
    dd = s3[0] + s3[1] + s3[2] + s3[3];

    float invz  = 1.0f / fmaxf(sqrtf(sz), c_eps);
    float invza = 1.0f / fmaxf(sqrtf(sa), c_eps);

    float4 o4 = make_float4(v.x * invz, v.y * invz, v.z * invz, v.w * invz);
    reinterpret_cast<float4*>(g_zn + (size_t)row * D)[t] = o4;

    if (t == 0) g_eadv[row] = expf(dd * invz * invza * c_invT);
}

// ---------------------------------------------------------------------------
// Main: warp per member slot s (adjacent warps share a class -> L1 reuse).
// 2-way member unroll for ILP. Block partial -> g_partial; ticket last-block
// does the deterministic fixed-tree final reduction into out[0].
// ---------------------------------------------------------------------------
__global__ void k_intra(float* __restrict__ out) {
    __shared__ float warp_loss[INTRA_THREADS / 32];
    __shared__ bool is_last;
    int s = (blockIdx.x * blockDim.x + threadIdx.x) >> 5;
    int lane = threadIdx.x & 31;
    int wid = threadIdx.x >> 5;

    int i = g_members[s];
    int c = g_lab[i];
    int off = g_offset[c];
    int cnt = g_count[c];

    const float4* zi = reinterpret_cast<const float4*>(g_zn + (size_t)i * D);
    float4 r0 = zi[lane], r1 = zi[lane + 32], r2 = zi[lane + 64], r3 = zi[lane + 96];

    float acc = 0.0f;
    int m = 0;
    for (; m + 2 <= cnt; m += 2) {
        int j0 = g_members[off + m];
        int j1 = g_members[off + m + 1];
        const float4* a = reinterpret_cast<const float4*>(g_zn + (size_t)j0 * D);
        const float4* b = reinterpret_cast<const float4*>(g_zn + (size_t)j1 * D);
        float s0 = 0.0f, s1 = 0.0f;
        float4 p, q;
        p = a[lane];       q = b[lane];
        s0 += r0.x*p.x + r0.y*p.y + r0.z*p.z + r0.w*p.w;
        s1 += r0.x*q.x + r0.y*q.y + r0.z*q.z + r0.w*q.w;
        p = a[lane + 32];  q = b[lane + 32];
        s0 += r1.x*p.x + r1.y*p.y + r1.z*p.z + r1.w*p.w;
        s1 += r1.x*q.x + r1.y*q.y + r1.z*q.z + r1.w*q.w;
        p = a[lane + 64];  q = b[lane + 64];
        s0 += r2.x*p.x + r2.y*p.y + r2.z*p.z + r2.w*p.w;
        s1 += r2.x*q.x + r2.y*q.y + r2.z*q.z + r2.w*q.w;
        p = a[lane + 96];  q = b[lane + 96];
        s0 += r3.x*p.x + r3.y*p.y + r3.z*p.z + r3.w*p.w;
        s1 += r3.x*q.x + r3.y*q.y + r3.z*q.z + r3.w*q.w;
#pragma unroll
        for (int o = 16; o; o >>= 1) {
            s0 += __shfl_xor_sync(0xffffffffu, s0, o);
            s1 += __shfl_xor_sync(0xffffffffu, s1, o);
        }
        float e0 = __expf(s0 * c_invT);
        float e1 = __expf(s1 * c_invT);
        acc += (j0 != i) ? e0 : 0.0f;
        acc += (j1 != i) ? e1 : 0.0f;
    }
    if (m < cnt) {
        int j0 = g_members[off + m];
        const float4* a = reinterpret_cast<const float4*>(g_zn + (size_t)j0 * D);
        float s0 = 0.0f;
        float4 p;
        p = a[lane];       s0 += r0.x*p.x + r0.y*p.y + r0.z*p.z + r0.w*p.w;
        p = a[lane + 32];  s0 += r1.x*p.x + r1.y*p.y + r1.z*p.z + r1.w*p.w;
        p = a[lane + 64];  s0 += r2.x*p.x + r2.y*p.y + r2.z*p.z + r2.w*p.w;
        p = a[lane + 96];  s0 += r3.x*p.x + r3.y*p.y + r3.z*p.z + r3.w*p.w;
#pragma unroll
        for (int o = 16; o; o >>= 1) s0 += __shfl_xor_sync(0xffffffffu, s0, o);
        acc += (j0 != i) ? __expf(s0 * c_invT) : 0.0f;
    }

    // per-warp loss -> block partial (fixed order => deterministic)
    if (lane == 0) warp_loss[wid] = log1pf(acc / g_eadv[i]);
    __syncthreads();
    if (threadIdx.x == 0) {
        float bsum = 0.0f;
#pragma unroll
        for (int ww = 0; ww < INTRA_THREADS / 32; ww++) bsum += warp_loss[ww];
        g_partial[blockIdx.x] = bsum;
        __threadfence();
        unsigned int ticket = atomicAdd(&g_done, 1u);
        is_last = (ticket == INTRA_BLOCKS - 1);
    }
    __syncthreads();

    // last-arriving block: deterministic fixed-tree reduction of 512 partials
    if (is_last) {
        __shared__ float sm[INTRA_THREADS];
        int t = threadIdx.x;
        __threadfence();
        sm[t] = g_partial[t] + g_partial[t + INTRA_THREADS];
        __syncthreads();
#pragma unroll
        for (int o = INTRA_THREADS / 2; o > 0; o >>= 1) {
            if (t < o) sm[t] += sm[t + o];
            __syncthreads();
        }
        if (t == 0) out[0] = sm[0] * (1.0f / (float)N);
    }
}

extern "C" void kernel_launch(void* const* d_in, const int* in_sizes, int n_in,
                              void* d_out, int out_size) {
    const float* z   = (const float*)d_in[0];
    const float* za  = (const float*)d_in[1];
    const int*   lab = (const int*)d_in[2];
    float* out = (float*)d_out;

    k_labels<<<1, 1024>>>(lab);
    k_norm<<<N, 128>>>(z, za);
    k_intra<<<INTRA_BLOCKS, INTRA_THREADS>>>(out);
}